// round 12
// baseline (speedup 1.0000x reference)
#include <cuda_runtime.h>
#include <cuda_bf16.h>
#include <cstdint>
#include <cfloat>

#define LEVELS 2
#define BATCH  16
#define DIM    256
#define TLEN   2048
#define NPTS   (BATCH * TLEN)       // 32768 points per level
#define KCODES 1024
#define NELEM  (BATCH * DIM * TLEN) // 8388608 per level
#define GATHER_BLOCKS (BATCH * (TLEN / 32))
#define TAU_S  0.004f               // ~11 sigma of split-bf16 HMMA error in s-space
#define NTILES (LEVELS * (NPTS / 64))   // 1024 work items

// ---------------- scratch (no allocations allowed) ----------------
__device__ float    g_bt[(size_t)LEVELS * DIM * KCODES];   // codebook transposed (refine)
__device__ float2   g_cninit[LEVELS * (KCODES / 2)];       // packed (-cn/2) pairs
__device__ float    g_partial[LEVELS][GATHER_BLOCKS];
__device__ int      g_idx[LEVELS][NPTS];
__device__ int      g_refine_count[LEVELS];
__device__ int      g_refine_list[LEVELS][NPTS];
__device__ int      g_tile_ctr;
// bf16 splits packed as u32 pairs (elem 2d in low half): [p][d] and [c][d]
__device__ unsigned g_xhi[(size_t)LEVELS * NPTS * (DIM / 2)];
__device__ unsigned g_xlo[(size_t)LEVELS * NPTS * (DIM / 2)];
__device__ unsigned g_ehi[(size_t)LEVELS * KCODES * (DIM / 2)];
__device__ unsigned g_elo[(size_t)LEVELS * KCODES * (DIM / 2)];

// ---------------- helpers ----------------
__device__ __forceinline__ void cp16(void* dst, const void* src) {
    unsigned s = (unsigned)__cvta_generic_to_shared(dst);
    asm volatile("cp.async.cg.shared.global [%0], [%1], 16;" :: "r"(s), "l"(src) : "memory");
}
#define CP_COMMIT() asm volatile("cp.async.commit_group;" ::: "memory")
#define CP_WAIT0()  asm volatile("cp.async.wait_group 0;" ::: "memory")

__device__ __forceinline__ void lda4(uint32_t r[4], uint32_t addr) {
    asm volatile("ldmatrix.sync.aligned.m8n8.x4.shared.b16 {%0,%1,%2,%3}, [%4];"
                 : "=r"(r[0]), "=r"(r[1]), "=r"(r[2]), "=r"(r[3]) : "r"(addr));
}
__device__ __forceinline__ void mma16816(float d[4], const uint32_t a[4], const uint32_t b[2]) {
    asm volatile("mma.sync.aligned.m16n8k16.row.col.f32.bf16.bf16.f32 "
                 "{%0,%1,%2,%3}, {%4,%5,%6,%7}, {%8,%9}, {%0,%1,%2,%3};"
                 : "+f"(d[0]), "+f"(d[1]), "+f"(d[2]), "+f"(d[3])
                 : "r"(a[0]), "r"(a[1]), "r"(a[2]), "r"(a[3]), "r"(b[0]), "r"(b[1]));
}

// ---------------- kernel: split+transpose h -> x_hi/x_lo bf16 [lvl][p][d] ----------------
__global__ __launch_bounds__(256)
void xsplit_kernel(const float* __restrict__ h_top, const float* __restrict__ h_bot) {
    __shared__ float s[32][65];
    int z = blockIdx.z, lvl = z >> 4, b = z & 15;
    const float* h = lvl ? h_bot : h_top;
    int t0 = blockIdx.x * 32, d0 = blockIdx.y * 64;
    int tid = threadIdx.x, lane = tid & 31, w = tid >> 5;
#pragma unroll
    for (int k = 0; k < 8; k++) {
        int dl = w + 8 * k;
        s[lane][dl] = h[((size_t)b * DIM + d0 + dl) * TLEN + t0 + lane];
    }
    __syncthreads();
    int pl = tid >> 3, q = tid & 7;
    int p = b * TLEN + t0 + pl;
    size_t rowbase = ((size_t)lvl * NPTS + p) * (DIM / 2) + (d0 >> 1);
#pragma unroll
    for (int k = 0; k < 4; k++) {
        int d2 = q + 8 * k;
        float v0 = s[pl][2 * d2], v1 = s[pl][2 * d2 + 1];
        __nv_bfloat16 h0 = __float2bfloat16(v0), h1 = __float2bfloat16(v1);
        __nv_bfloat16 l0 = __float2bfloat16(v0 - __bfloat162float(h0));
        __nv_bfloat16 l1 = __float2bfloat16(v1 - __bfloat162float(h1));
        g_xhi[rowbase + d2] = ((unsigned)__bfloat16_as_ushort(h1) << 16) | __bfloat16_as_ushort(h0);
        g_xlo[rowbase + d2] = ((unsigned)__bfloat16_as_ushort(l1) << 16) | __bfloat16_as_ushort(l0);
    }
}

// ---------------- kernel: codebook split + (-cn/2) + counter resets ----------------
__global__ __launch_bounds__(256)
void ecnorm_kernel(const float* __restrict__ cb_top, const float* __restrict__ cb_bot) {
    __shared__ float s8[8];
    int lvl = blockIdx.y;
    if (blockIdx.x == 0 && threadIdx.x == 0) {
        g_refine_count[lvl] = 0;
        if (lvl == 0) g_tile_ctr = 0;
    }
    const float* cb = lvl ? cb_bot : cb_top;
    int w = threadIdx.x >> 5, lane = threadIdx.x & 31;
    int c = blockIdx.x * 8 + w;
    const float* row = cb + (size_t)c * DIM;
    size_t rowbase = ((size_t)lvl * KCODES + c) * (DIM / 2);
    float sacc = 0.f;
#pragma unroll
    for (int k = 0; k < 4; k++) {
        int d2 = lane + 32 * k;
        float v0 = row[2 * d2], v1 = row[2 * d2 + 1];
        sacc = fmaf(v0, v0, sacc);
        sacc = fmaf(v1, v1, sacc);
        __nv_bfloat16 h0 = __float2bfloat16(v0), h1 = __float2bfloat16(v1);
        __nv_bfloat16 l0 = __float2bfloat16(v0 - __bfloat162float(h0));
        __nv_bfloat16 l1 = __float2bfloat16(v1 - __bfloat162float(h1));
        g_ehi[rowbase + d2] = ((unsigned)__bfloat16_as_ushort(h1) << 16) | __bfloat16_as_ushort(h0);
        g_elo[rowbase + d2] = ((unsigned)__bfloat16_as_ushort(l1) << 16) | __bfloat16_as_ushort(l0);
    }
#pragma unroll
    for (int o = 16; o; o >>= 1) sacc += __shfl_down_sync(0xffffffffu, sacc, o);
    if (lane == 0) s8[w] = sacc;
    __syncthreads();
    if (threadIdx.x < 4)
        g_cninit[lvl * (KCODES / 2) + blockIdx.x * 4 + threadIdx.x] =
            make_float2(-0.5f * s8[2 * threadIdx.x], -0.5f * s8[2 * threadIdx.x + 1]);
}

// ---------------- kernel: transpose codebook to [d][c] (refine uses it) ----------------
__global__ __launch_bounds__(256)
void btrans_kernel(const float* __restrict__ cb_top, const float* __restrict__ cb_bot) {
    __shared__ float s[32][33];
    int lvl = blockIdx.z;
    const float* cb = lvl ? cb_bot : cb_top;
    int c0 = blockIdx.x * 32, d0 = blockIdx.y * 32;
    int lx = threadIdx.x & 31, ly = threadIdx.x >> 5;
#pragma unroll
    for (int k = 0; k < 4; k++)
        s[ly + 8 * k][lx] = cb[(size_t)(c0 + ly + 8 * k) * DIM + d0 + lx];
    __syncthreads();
#pragma unroll
    for (int k = 0; k < 4; k++)
        g_bt[((size_t)lvl * DIM + d0 + ly + 8 * k) * KCODES + c0 + lx] = s[lx][ly + 8 * k];
}

// ---------------- argmin GEMM via mma.sync bf16: persistent CTAs, 2 chunks/barrier ----------------
// smem: A_hi 32KB | A_lo 32KB | B ring 4 x 10KB (rows padded to 80B) => 104KB/CTA, 2 CTAs/SM
#define SM_AHI 0
#define SM_ALO 32768
#define SM_B   65536
#define SM_RED 65536             // reduce scratch reuses B ring after mainloop
#define ARG_SMEM (65536 + 4 * 10240)

__device__ __forceinline__ void issueB(char* smem, int s, int tid, size_t L) {
    int nt = s >> 4, ch = s & 15, buf = s & 3;
    int row = tid >> 1, sg = tid & 1;
    char* bb = smem + SM_B + buf * 10240;
    size_t src = (L + nt * 128 + row) * (size_t)128 + ch * 8 + sg * 4;
    cp16(bb + row * 80 + sg * 16,      &g_ehi[src]);
    cp16(bb + row * 80 + 32 + sg * 16, &g_elo[src]);
    CP_COMMIT();
}

__global__ __launch_bounds__(256, 2)
void argmin_kernel() {
    extern __shared__ __align__(128) char smem[];
    __shared__ int s_pos;
    int tid = threadIdx.x, lane = tid & 31, wid = tid >> 5;
    int wm = wid >> 2, wn = wid & 3;           // 2 warp-rows (32M) x 4 warp-cols (32N)
    uint32_t sb = (uint32_t)__cvta_generic_to_shared(smem);

    for (;;) {
        if (tid == 0) s_pos = atomicAdd(&g_tile_ctr, 1);
        __syncthreads();                        // s_pos visible; prev tile's smem use done
        int pos = s_pos;
        if (pos >= NTILES) break;
        int lvl = pos >> 9;
        int m0 = (pos & 511) * 64;
        size_t XL = (size_t)lvl * NPTS;
        size_t EL = (size_t)lvl * KCODES;

        // ---- prologue: A (hi+lo, 64 rows) resident swizzled smem; then B chunks 0,1 ----
#pragma unroll
        for (int i = 0; i < 8; i++) {
            int idx = tid + i * 256;            // 2048 segs per part
            int row = idx >> 5, seg = idx & 31;
            int soff = ((seg ^ (row & 7)) << 4);
            size_t src = (XL + m0 + row) * (size_t)128 + seg * 4;
            cp16(smem + SM_AHI + row * 512 + soff, &g_xhi[src]);
            cp16(smem + SM_ALO + row * 512 + soff, &g_xlo[src]);
        }
        CP_COMMIT();
        issueB(smem, 0, tid, EL);
        issueB(smem, 1, tid, EL);

        float tb[4], t2[4];
        int   ti[4];
#pragma unroll
        for (int r = 0; r < 4; r++) { tb[r] = -FLT_MAX; t2[r] = -FLT_MAX; ti[r] = 0; }

        float acc[2][4][4];

#pragma unroll 1
        for (int ss = 0; ss < 64; ss++) {
            int nt = ss >> 3;
            if ((ss & 7) == 0) {
                // init accumulators with -cn/2 (per-column)
#pragma unroll
                for (int j = 0; j < 4; j++) {
                    int c0 = nt * 128 + wn * 32 + j * 8 + (lane & 3) * 2;
                    float2 ci = g_cninit[lvl * (KCODES / 2) + (c0 >> 1)];
#pragma unroll
                    for (int mi = 0; mi < 2; mi++) {
                        acc[mi][j][0] = ci.x; acc[mi][j][1] = ci.y;
                        acc[mi][j][2] = ci.x; acc[mi][j][3] = ci.y;
                    }
                }
            }

            CP_WAIT0();                         // chunks 2ss, 2ss+1 (and A on ss=0) complete
            __syncthreads();                    // ring slot reuse safety
            int s2 = 2 * ss + 2;
            if (s2 < 128) {                     // slots (s2&3, s2+1&3) disjoint from consumed pair
                issueB(smem, s2, tid, EL);
                issueB(smem, s2 + 1, tid, EL);
            }

#pragma unroll
            for (int half = 0; half < 2; half++) {
                int s = 2 * ss + half;
                int ch = s & 15;
                uint32_t bb = sb + SM_B + (s & 3) * 10240;

                // A fragments: 2 m-tiles (16 rows each), hi + lo
                uint32_t ah[2][4], al[2][4];
#pragma unroll
                for (int mi = 0; mi < 2; mi++) {
                    int p = wm * 32 + mi * 16 + (lane & 7) + ((lane >> 3) & 1) * 8;
                    int seg = ch * 2 + (lane >> 4);
                    uint32_t off = p * 512 + ((seg ^ (p & 7)) << 4);
                    lda4(ah[mi], sb + SM_AHI + off);
                    lda4(al[mi], sb + SM_ALO + off);
                }

                // B fragments via x4
                uint32_t bh[8], bl[8];
                {
                    int g = lane >> 3, i = lane & 7;
                    uint32_t a0 = bb + (uint32_t)(wn * 32 + (g >> 1) * 8 + i) * 80 + (g & 1) * 16;
                    lda4(&bh[0], a0);
                    lda4(&bh[4], a0 + 16 * 80);
                    lda4(&bl[0], a0 + 32);
                    lda4(&bl[4], a0 + 16 * 80 + 32);
                }
#pragma unroll
                for (int j = 0; j < 4; j++) {
#pragma unroll
                    for (int mi = 0; mi < 2; mi++) {
                        mma16816(acc[mi][j], ah[mi], &bh[2 * j]);
                        mma16816(acc[mi][j], al[mi], &bh[2 * j]);
                        mma16816(acc[mi][j], ah[mi], &bl[2 * j]);
                    }
                }
            }

            if ((ss & 7) == 7) {
                // fold N-tile into running per-row top-2 (ascending c -> first-min tiebreak)
#pragma unroll
                for (int j = 0; j < 4; j++) {
                    int cbase = nt * 128 + wn * 32 + j * 8 + (lane & 3) * 2;
#pragma unroll
                    for (int mi = 0; mi < 2; mi++)
#pragma unroll
                        for (int rh = 0; rh < 2; rh++) {
                            int r = mi * 2 + rh;
#pragma unroll
                            for (int cc = 0; cc < 2; cc++) {
                                float v = acc[mi][j][rh * 2 + cc];
                                int c = cbase + cc;
                                if (v > tb[r]) { t2[r] = tb[r]; tb[r] = v; ti[r] = c; }
                                else if (v > t2[r]) t2[r] = v;
                            }
                        }
                }
            }
        }

        // quad merge (4 lanes share each row)
#pragma unroll
        for (int k = 1; k <= 2; k <<= 1) {
#pragma unroll
            for (int r = 0; r < 4; r++) {
                float ob = __shfl_xor_sync(0xffffffffu, tb[r], k);
                float o2 = __shfl_xor_sync(0xffffffffu, t2[r], k);
                int   oi = __shfl_xor_sync(0xffffffffu, ti[r], k);
                if (ob > tb[r] || (ob == tb[r] && oi < ti[r])) {
                    t2[r] = fmaxf(tb[r], o2); tb[r] = ob; ti[r] = oi;
                } else {
                    t2[r] = fmaxf(t2[r], ob);
                }
            }
        }

        __syncthreads();                         // B ring drained; reuse as reduce scratch
        float* rv  = (float*)(smem + SM_RED);    // 64 rows x 4 wn
        float* r2v = rv + 256;
        int*   rix = (int*)(r2v + 256);
        if ((lane & 3) == 0) {
#pragma unroll
            for (int r = 0; r < 4; r++) {
                int row = wm * 32 + (r >> 1) * 16 + (r & 1) * 8 + (lane >> 2);
                rv[row * 4 + wn]  = tb[r];
                r2v[row * 4 + wn] = t2[r];
                rix[row * 4 + wn] = ti[r];
            }
        }
        __syncthreads();
        if (tid < 64) {
            float bv = rv[tid * 4];
            float bs = r2v[tid * 4];
            int   bi = rix[tid * 4];
#pragma unroll
            for (int x = 1; x < 4; x++) {
                float v  = rv[tid * 4 + x];
                float v2 = r2v[tid * 4 + x];
                int   ii = rix[tid * 4 + x];
                if (v > bv || (v == bv && ii < bi)) { bs = fmaxf(bv, v2); bv = v; bi = ii; }
                else                                 bs = fmaxf(bs, v);
            }
            g_idx[lvl][m0 + tid] = bi;
            if (bv - bs < TAU_S) {
                int p2 = atomicAdd(&g_refine_count[lvl], 1);
                g_refine_list[lvl][p2] = m0 + tid;
            }
        }
    }
}

// ---------------- kernel: double-f32 exact refinement (1 point/block, 1 code/thread) ----------------
__global__ __launch_bounds__(1024)
void refine_kernel(const float* __restrict__ h_top, const float* __restrict__ h_bot) {
    int lvl = blockIdx.y;
    const float* h = lvl ? h_bot : h_top;
    const float* bt = g_bt + (size_t)lvl * DIM * KCODES;
    int cnt = g_refine_count[lvl];

    __shared__ float xs[DIM];
    __shared__ float rh[1024], rl[1024];
    __shared__ int   rix[1024];

    int tid = threadIdx.x;
    int c = tid;

    for (int e = blockIdx.x; e < cnt; e += gridDim.x) {
        int p = g_refine_list[lvl][e];
        int b = p / TLEN, t = p % TLEN;
        __syncthreads();
        if (tid < DIM)
            xs[tid] = h[((size_t)b * DIM + tid) * TLEN + t];
        __syncthreads();

        float hi = 0.f, lo = 0.f;
#pragma unroll 8
        for (int d = 0; d < DIM; d++) {
            float ev = bt[(size_t)d * KCODES + c];
            float x  = xs[d];
            float s  = x - ev;
            float bb = s - x;
            float err = (x - (s - bb)) + ((-ev) - bb);
            float pq = s * s;
            float pe = fmaf(s, s, -pq);
            float cross = fmaf(2.f * s, err, fmaf(err, err, pe));
            float t1  = hi + pq;
            float bb2 = t1 - hi;
            float e2  = (hi - (t1 - bb2)) + (pq - bb2);
            hi = t1;
            lo += e2 + cross;
        }
        float th = hi + lo;
        float tl = lo - (th - hi);

        rh[tid] = th; rl[tid] = tl; rix[tid] = c;
        __syncthreads();
#pragma unroll
        for (int s = 512; s; s >>= 1) {
            if (tid < s) {
                float oh = rh[tid + s], ol = rl[tid + s];
                int   oi = rix[tid + s];
                float mh = rh[tid], ml = rl[tid];
                int   mi = rix[tid];
                if (oh < mh || (oh == mh && (ol < ml || (ol == ml && oi < mi)))) {
                    rh[tid] = oh; rl[tid] = ol; rix[tid] = oi;
                }
            }
            __syncthreads();
        }
        if (tid == 0) g_idx[lvl][p] = rix[0];
    }
}

// ---------------- kernel: gather z_q + per-block loss partials ----------------
__global__ __launch_bounds__(256)
void gather_kernel(const float* __restrict__ h_top, const float* __restrict__ h_bot,
                   const float* __restrict__ cb_top, const float* __restrict__ cb_bot,
                   float* __restrict__ out) {
    int lvl = blockIdx.z;
    const float* h  = lvl ? h_bot  : h_top;
    const float* cb = lvl ? cb_bot : cb_top;
    float* z = out + (size_t)lvl * NELEM;

    int b = blockIdx.y;
    int t0 = blockIdx.x * 32;
    int tid = threadIdx.x;

    __shared__ int   sidx[32];
    __shared__ float sh[32 * 33];
    __shared__ float red[256];

    if (tid < 32) sidx[tid] = g_idx[lvl][b * TLEN + t0 + tid];
    __syncthreads();

    float lacc = 0.f;
    int j2 = tid >> 3, l8 = tid & 7;

    for (int dc = 0; dc < DIM; dc += 32) {
        float4 v = *(const float4*)(cb + (size_t)sidx[j2] * DIM + dc + l8 * 4);
        sh[(l8 * 4 + 0) * 33 + j2] = v.x;
        sh[(l8 * 4 + 1) * 33 + j2] = v.y;
        sh[(l8 * 4 + 2) * 33 + j2] = v.z;
        sh[(l8 * 4 + 3) * 33 + j2] = v.w;
        __syncthreads();
#pragma unroll
        for (int it = 0; it < 4; it++) {
            int i = tid + it * 256;
            int dl = i >> 5, j = i & 31;
            size_t off = ((size_t)b * DIM + dc + dl) * TLEN + t0 + j;
            float zz = sh[dl * 33 + j];
            z[off] = zz;
            float e = h[off] - zz;
            lacc = fmaf(e, e, lacc);
        }
        __syncthreads();
    }

    red[tid] = lacc;
    __syncthreads();
#pragma unroll
    for (int s = 128; s; s >>= 1) {
        if (tid < s) red[tid] += red[tid + s];
        __syncthreads();
    }
    if (tid == 0) g_partial[lvl][blockIdx.y * (TLEN / 32) + blockIdx.x] = red[0];
}

// ---------------- kernel: finalize scalars ----------------
__global__ __launch_bounds__(1024)
void finalize_kernel(float* __restrict__ out) {
    __shared__ int   hist[KCODES];
    __shared__ float red[1024];
    int tid = threadIdx.x;

    float sums[2];
#pragma unroll
    for (int lvl = 0; lvl < 2; lvl++) {
        red[tid] = g_partial[lvl][tid];
        __syncthreads();
        for (int s = 512; s; s >>= 1) {
            if (tid < s) red[tid] += red[tid + s];
            __syncthreads();
        }
        sums[lvl] = red[0];
        __syncthreads();
    }
    float loss = sums[0] * (1.f / (float)NELEM) + sums[1] * (1.f / (float)NELEM);

    float ppl[2];
#pragma unroll
    for (int lvl = 0; lvl < 2; lvl++) {
        hist[tid] = 0;
        __syncthreads();
#pragma unroll
        for (int i = 0; i < NPTS / 1024; i++)
            atomicAdd(&hist[g_idx[lvl][i * 1024 + tid]], 1);
        __syncthreads();
        float p = (float)hist[tid] * (1.f / (float)NPTS);
        red[tid] = p * logf(p + 1e-10f);
        __syncthreads();
        for (int s = 512; s; s >>= 1) {
            if (tid < s) red[tid] += red[tid + s];
            __syncthreads();
        }
        ppl[lvl] = expf(-red[0]);
        __syncthreads();
    }

    if (tid == 0) {
        size_t base = (size_t)2 * NELEM;
        out[base + 0] = loss;
        out[base + 1] = loss;
        out[base + 2] = ppl[0];
        out[base + 3] = ppl[1];
    }
}

// ---------------- launcher ----------------
extern "C" void kernel_launch(void* const* d_in, const int* in_sizes, int n_in,
                              void* d_out, int out_size) {
    const float* h_top  = (const float*)d_in[0];
    const float* h_bot  = (const float*)d_in[1];
    const float* cb_top = (const float*)d_in[2];
    const float* cb_bot = (const float*)d_in[3];
    float* out = (float*)d_out;

    cudaFuncSetAttribute(argmin_kernel,
                         cudaFuncAttributeMaxDynamicSharedMemorySize, ARG_SMEM);

    xsplit_kernel<<<dim3(TLEN / 32, DIM / 64, BATCH * LEVELS), 256>>>(h_top, h_bot);
    ecnorm_kernel<<<dim3(KCODES / 8, LEVELS), 256>>>(cb_top, cb_bot);
    btrans_kernel<<<dim3(KCODES / 32, DIM / 32, LEVELS), 256>>>(cb_top, cb_bot);
    argmin_kernel<<<296, 256, ARG_SMEM>>>();
    refine_kernel<<<dim3(512, LEVELS), 1024>>>(h_top, h_bot);
    gather_kernel<<<dim3(TLEN / 32, BATCH, LEVELS), 256>>>(h_top, h_bot, cb_top, cb_bot, out);
    finalize_kernel<<<1, 1024>>>(out);
}

// round 13
// speedup vs baseline: 1.0423x; 1.0423x over previous
#include <cuda_runtime.h>
#include <cuda_bf16.h>
#include <cstdint>
#include <cfloat>

#define LEVELS 2
#define BATCH  16
#define DIM    256
#define TLEN   2048
#define NPTS   (BATCH * TLEN)       // 32768 points per level
#define KCODES 1024
#define NELEM  (BATCH * DIM * TLEN) // 8388608 per level
#define GATHER_BLOCKS (BATCH * (TLEN / 32))
#define TAU_S  0.004f               // ~11 sigma of split-bf16 HMMA error in s-space
#define NTILES (LEVELS * (NPTS / 64))   // 1024 work items

// ---------------- scratch (no allocations allowed) ----------------
__device__ float    g_bt[(size_t)LEVELS * DIM * KCODES];   // codebook transposed (refine)
__device__ float2   g_cninit[LEVELS * (KCODES / 2)];       // packed (-cn/2) pairs
__device__ float    g_partial[LEVELS][GATHER_BLOCKS];
__device__ int      g_idx[LEVELS][NPTS];
__device__ int      g_refine_count[LEVELS];
__device__ int      g_refine_list[LEVELS][NPTS];
__device__ int      g_tile_ctr;
// bf16 splits packed as u32 pairs (elem 2d in low half): [p][d] and [c][d]
__device__ unsigned g_xhi[(size_t)LEVELS * NPTS * (DIM / 2)];
__device__ unsigned g_xlo[(size_t)LEVELS * NPTS * (DIM / 2)];
__device__ unsigned g_ehi[(size_t)LEVELS * KCODES * (DIM / 2)];
__device__ unsigned g_elo[(size_t)LEVELS * KCODES * (DIM / 2)];

// ---------------- helpers ----------------
__device__ __forceinline__ void cp16(void* dst, const void* src) {
    unsigned s = (unsigned)__cvta_generic_to_shared(dst);
    asm volatile("cp.async.cg.shared.global [%0], [%1], 16;" :: "r"(s), "l"(src) : "memory");
}
#define CP_COMMIT() asm volatile("cp.async.commit_group;" ::: "memory")
#define CP_WAIT2()  asm volatile("cp.async.wait_group 2;" ::: "memory")
#define CP_WAIT0()  asm volatile("cp.async.wait_group 0;" ::: "memory")

__device__ __forceinline__ void lda4(uint32_t r[4], uint32_t addr) {
    asm volatile("ldmatrix.sync.aligned.m8n8.x4.shared.b16 {%0,%1,%2,%3}, [%4];"
                 : "=r"(r[0]), "=r"(r[1]), "=r"(r[2]), "=r"(r[3]) : "r"(addr));
}
__device__ __forceinline__ void mma16816(float d[4], const uint32_t a[4], const uint32_t b[2]) {
    asm volatile("mma.sync.aligned.m16n8k16.row.col.f32.bf16.bf16.f32 "
                 "{%0,%1,%2,%3}, {%4,%5,%6,%7}, {%8,%9}, {%0,%1,%2,%3};"
                 : "+f"(d[0]), "+f"(d[1]), "+f"(d[2]), "+f"(d[3])
                 : "r"(a[0]), "r"(a[1]), "r"(a[2]), "r"(a[3]), "r"(b[0]), "r"(b[1]));
}

// ---------------- kernel: split+transpose h -> x_hi/x_lo bf16 [lvl][p][d] ----------------
__global__ __launch_bounds__(256)
void xsplit_kernel(const float* __restrict__ h_top, const float* __restrict__ h_bot) {
    __shared__ float s[32][65];
    int z = blockIdx.z, lvl = z >> 4, b = z & 15;
    const float* h = lvl ? h_bot : h_top;
    int t0 = blockIdx.x * 32, d0 = blockIdx.y * 64;
    int tid = threadIdx.x, lane = tid & 31, w = tid >> 5;
#pragma unroll
    for (int k = 0; k < 8; k++) {
        int dl = w + 8 * k;
        s[lane][dl] = h[((size_t)b * DIM + d0 + dl) * TLEN + t0 + lane];
    }
    __syncthreads();
    int pl = tid >> 3, q = tid & 7;
    int p = b * TLEN + t0 + pl;
    size_t rowbase = ((size_t)lvl * NPTS + p) * (DIM / 2) + (d0 >> 1);
#pragma unroll
    for (int k = 0; k < 4; k++) {
        int d2 = q + 8 * k;
        float v0 = s[pl][2 * d2], v1 = s[pl][2 * d2 + 1];
        __nv_bfloat16 h0 = __float2bfloat16(v0), h1 = __float2bfloat16(v1);
        __nv_bfloat16 l0 = __float2bfloat16(v0 - __bfloat162float(h0));
        __nv_bfloat16 l1 = __float2bfloat16(v1 - __bfloat162float(h1));
        g_xhi[rowbase + d2] = ((unsigned)__bfloat16_as_ushort(h1) << 16) | __bfloat16_as_ushort(h0);
        g_xlo[rowbase + d2] = ((unsigned)__bfloat16_as_ushort(l1) << 16) | __bfloat16_as_ushort(l0);
    }
}

// ---------------- kernel: codebook split + (-cn/2) + counter resets ----------------
__global__ __launch_bounds__(256)
void ecnorm_kernel(const float* __restrict__ cb_top, const float* __restrict__ cb_bot) {
    __shared__ float s8[8];
    int lvl = blockIdx.y;
    if (blockIdx.x == 0 && threadIdx.x == 0) {
        g_refine_count[lvl] = 0;
        if (lvl == 0) g_tile_ctr = 0;
    }
    const float* cb = lvl ? cb_bot : cb_top;
    int w = threadIdx.x >> 5, lane = threadIdx.x & 31;
    int c = blockIdx.x * 8 + w;
    const float* row = cb + (size_t)c * DIM;
    size_t rowbase = ((size_t)lvl * KCODES + c) * (DIM / 2);
    float sacc = 0.f;
#pragma unroll
    for (int k = 0; k < 4; k++) {
        int d2 = lane + 32 * k;
        float v0 = row[2 * d2], v1 = row[2 * d2 + 1];
        sacc = fmaf(v0, v0, sacc);
        sacc = fmaf(v1, v1, sacc);
        __nv_bfloat16 h0 = __float2bfloat16(v0), h1 = __float2bfloat16(v1);
        __nv_bfloat16 l0 = __float2bfloat16(v0 - __bfloat162float(h0));
        __nv_bfloat16 l1 = __float2bfloat16(v1 - __bfloat162float(h1));
        g_ehi[rowbase + d2] = ((unsigned)__bfloat16_as_ushort(h1) << 16) | __bfloat16_as_ushort(h0);
        g_elo[rowbase + d2] = ((unsigned)__bfloat16_as_ushort(l1) << 16) | __bfloat16_as_ushort(l0);
    }
#pragma unroll
    for (int o = 16; o; o >>= 1) sacc += __shfl_down_sync(0xffffffffu, sacc, o);
    if (lane == 0) s8[w] = sacc;
    __syncthreads();
    if (threadIdx.x < 4)
        g_cninit[lvl * (KCODES / 2) + blockIdx.x * 4 + threadIdx.x] =
            make_float2(-0.5f * s8[2 * threadIdx.x], -0.5f * s8[2 * threadIdx.x + 1]);
}

// ---------------- kernel: transpose codebook to [d][c] (refine uses it) ----------------
__global__ __launch_bounds__(256)
void btrans_kernel(const float* __restrict__ cb_top, const float* __restrict__ cb_bot) {
    __shared__ float s[32][33];
    int lvl = blockIdx.z;
    const float* cb = lvl ? cb_bot : cb_top;
    int c0 = blockIdx.x * 32, d0 = blockIdx.y * 32;
    int lx = threadIdx.x & 31, ly = threadIdx.x >> 5;
#pragma unroll
    for (int k = 0; k < 4; k++)
        s[ly + 8 * k][lx] = cb[(size_t)(c0 + ly + 8 * k) * DIM + d0 + lx];
    __syncthreads();
#pragma unroll
    for (int k = 0; k < 4; k++)
        g_bt[((size_t)lvl * DIM + d0 + ly + 8 * k) * KCODES + c0 + lx] = s[lx][ly + 8 * k];
}

// ---------------- argmin GEMM via mma.sync bf16: R11 pipeline + persistent CTAs ----------------
// smem: A_hi 32KB | A_lo 32KB | B ring 4 x 10KB (rows padded to 80B) => 104KB/CTA, 2 CTAs/SM
#define SM_AHI 0
#define SM_ALO 32768
#define SM_B   65536
#define SM_RED 65536             // reduce scratch reuses B ring after mainloop
#define ARG_SMEM (65536 + 4 * 10240)

__device__ __forceinline__ void issueB(char* smem, int s, int tid, size_t L) {
    int nt = s >> 4, ch = s & 15, buf = s & 3;
    int row = tid >> 1, sg = tid & 1;
    char* bb = smem + SM_B + buf * 10240;
    size_t src = (L + nt * 128 + row) * (size_t)128 + ch * 8 + sg * 4;
    cp16(bb + row * 80 + sg * 16,      &g_ehi[src]);
    cp16(bb + row * 80 + 32 + sg * 16, &g_elo[src]);
    CP_COMMIT();
}

__global__ __launch_bounds__(256, 2)
void argmin_kernel() {
    extern __shared__ __align__(128) char smem[];
    __shared__ int s_pos;
    int tid = threadIdx.x, lane = tid & 31, wid = tid >> 5;
    int wm = wid >> 2, wn = wid & 3;           // 2 warp-rows (32M) x 4 warp-cols (32N)
    uint32_t sb = (uint32_t)__cvta_generic_to_shared(smem);

    for (;;) {
        if (tid == 0) s_pos = atomicAdd(&g_tile_ctr, 1);
        __syncthreads();                        // s_pos visible; prev tile smem use done
        int pos = s_pos;
        if (pos >= NTILES) break;
        int lvl = pos >> 9;
        int m0 = (pos & 511) * 64;
        size_t XL = (size_t)lvl * NPTS;
        size_t EL = (size_t)lvl * KCODES;

        // ---- prologue: A (hi+lo, 64 rows) resident swizzled smem; then B chunks 0..2 ----
#pragma unroll
        for (int i = 0; i < 8; i++) {
            int idx = tid + i * 256;            // 2048 segs per part
            int row = idx >> 5, seg = idx & 31;
            int soff = ((seg ^ (row & 7)) << 4);
            size_t src = (XL + m0 + row) * (size_t)128 + seg * 4;
            cp16(smem + SM_AHI + row * 512 + soff, &g_xhi[src]);
            cp16(smem + SM_ALO + row * 512 + soff, &g_xlo[src]);
        }
        CP_COMMIT();
        issueB(smem, 0, tid, EL);
        issueB(smem, 1, tid, EL);
        issueB(smem, 2, tid, EL);

        float tb[4], t2[4];
        int   ti[4];
#pragma unroll
        for (int r = 0; r < 4; r++) { tb[r] = -FLT_MAX; t2[r] = -FLT_MAX; ti[r] = 0; }

#pragma unroll 1
        for (int nt = 0; nt < 8; nt++) {
            // init accumulators with -cn/2 (per-column)
            float acc[2][4][4];
#pragma unroll
            for (int j = 0; j < 4; j++) {
                int c0 = nt * 128 + wn * 32 + j * 8 + (lane & 3) * 2;
                float2 ci = g_cninit[lvl * (KCODES / 2) + (c0 >> 1)];
#pragma unroll
                for (int mi = 0; mi < 2; mi++) {
                    acc[mi][j][0] = ci.x; acc[mi][j][1] = ci.y;
                    acc[mi][j][2] = ci.x; acc[mi][j][3] = ci.y;
                }
            }

#pragma unroll 1
            for (int ch = 0; ch < 16; ch++) {
                int s = nt * 16 + ch;
                if (s < 125) CP_WAIT2();      // groups s+1, s+2 pending; s complete
                else         CP_WAIT0();      // tail: drain (last 3 chunks)
                __syncthreads();
                if (s < 125) issueB(smem, s + 3, tid, EL);   // slot (s-1)&3, safe post-sync
                uint32_t bb = sb + SM_B + (s & 3) * 10240;

                // A fragments: 2 m-tiles (16 rows each), hi + lo
                uint32_t ah[2][4], al[2][4];
#pragma unroll
                for (int mi = 0; mi < 2; mi++) {
                    int p = wm * 32 + mi * 16 + (lane & 7) + ((lane >> 3) & 1) * 8;
                    int seg = ch * 2 + (lane >> 4);
                    uint32_t off = p * 512 + ((seg ^ (p & 7)) << 4);
                    lda4(ah[mi], sb + SM_AHI + off);
                    lda4(al[mi], sb + SM_ALO + off);
                }

                // B fragments via x4: lane-group g -> (n-tile g>>1, k-half g&1)
                uint32_t bh[8], bl[8];
                {
                    int g = lane >> 3, i = lane & 7;
                    uint32_t a0 = bb + (uint32_t)(wn * 32 + (g >> 1) * 8 + i) * 80 + (g & 1) * 16;
                    lda4(&bh[0], a0);                 // n-tiles 0,1
                    lda4(&bh[4], a0 + 16 * 80);       // n-tiles 2,3
                    lda4(&bl[0], a0 + 32);
                    lda4(&bl[4], a0 + 16 * 80 + 32);
                }
#pragma unroll
                for (int j = 0; j < 4; j++) {
#pragma unroll
                    for (int mi = 0; mi < 2; mi++) {
                        mma16816(acc[mi][j], ah[mi], &bh[2 * j]);
                        mma16816(acc[mi][j], al[mi], &bh[2 * j]);
                        mma16816(acc[mi][j], ah[mi], &bl[2 * j]);
                    }
                }
            }

            // fold N-tile into running per-row top-2 (ascending c -> first-min tiebreak)
#pragma unroll
            for (int j = 0; j < 4; j++) {
                int cbase = nt * 128 + wn * 32 + j * 8 + (lane & 3) * 2;
#pragma unroll
                for (int mi = 0; mi < 2; mi++)
#pragma unroll
                    for (int rh = 0; rh < 2; rh++) {
                        int r = mi * 2 + rh;
#pragma unroll
                        for (int cc = 0; cc < 2; cc++) {
                            float v = acc[mi][j][rh * 2 + cc];
                            int c = cbase + cc;
                            if (v > tb[r]) { t2[r] = tb[r]; tb[r] = v; ti[r] = c; }
                            else if (v > t2[r]) t2[r] = v;
                        }
                    }
            }
        }

        // quad merge (4 lanes share each row)
#pragma unroll
        for (int k = 1; k <= 2; k <<= 1) {
#pragma unroll
            for (int r = 0; r < 4; r++) {
                float ob = __shfl_xor_sync(0xffffffffu, tb[r], k);
                float o2 = __shfl_xor_sync(0xffffffffu, t2[r], k);
                int   oi = __shfl_xor_sync(0xffffffffu, ti[r], k);
                if (ob > tb[r] || (ob == tb[r] && oi < ti[r])) {
                    t2[r] = fmaxf(tb[r], o2); tb[r] = ob; ti[r] = oi;
                } else {
                    t2[r] = fmaxf(t2[r], ob);
                }
            }
        }

        __syncthreads();                         // B ring drained; reuse as reduce scratch
        float* rv  = (float*)(smem + SM_RED);    // 64 rows x 4 wn
        float* r2v = rv + 256;
        int*   rix = (int*)(r2v + 256);
        if ((lane & 3) == 0) {
#pragma unroll
            for (int r = 0; r < 4; r++) {
                int row = wm * 32 + (r >> 1) * 16 + (r & 1) * 8 + (lane >> 2);
                rv[row * 4 + wn]  = tb[r];
                r2v[row * 4 + wn] = t2[r];
                rix[row * 4 + wn] = ti[r];
            }
        }
        __syncthreads();
        if (tid < 64) {
            float bv = rv[tid * 4];
            float bs = r2v[tid * 4];
            int   bi = rix[tid * 4];
#pragma unroll
            for (int x = 1; x < 4; x++) {
                float v  = rv[tid * 4 + x];
                float v2 = r2v[tid * 4 + x];
                int   ii = rix[tid * 4 + x];
                if (v > bv || (v == bv && ii < bi)) { bs = fmaxf(bv, v2); bv = v; bi = ii; }
                else                                 bs = fmaxf(bs, v);
            }
            g_idx[lvl][m0 + tid] = bi;
            if (bv - bs < TAU_S) {
                int p2 = atomicAdd(&g_refine_count[lvl], 1);
                g_refine_list[lvl][p2] = m0 + tid;
            }
        }
    }
}

// ---------------- kernel: double-f32 exact refinement (1 point/block, 1 code/thread) ----------------
__global__ __launch_bounds__(1024)
void refine_kernel(const float* __restrict__ h_top, const float* __restrict__ h_bot) {
    int lvl = blockIdx.y;
    const float* h = lvl ? h_bot : h_top;
    const float* bt = g_bt + (size_t)lvl * DIM * KCODES;
    int cnt = g_refine_count[lvl];

    __shared__ float xs[DIM];
    __shared__ float rh[1024], rl[1024];
    __shared__ int   rix[1024];

    int tid = threadIdx.x;
    int c = tid;

    for (int e = blockIdx.x; e < cnt; e += gridDim.x) {
        int p = g_refine_list[lvl][e];
        int b = p / TLEN, t = p % TLEN;
        __syncthreads();
        if (tid < DIM)
            xs[tid] = h[((size_t)b * DIM + tid) * TLEN + t];
        __syncthreads();

        float hi = 0.f, lo = 0.f;
#pragma unroll 8
        for (int d = 0; d < DIM; d++) {
            float ev = bt[(size_t)d * KCODES + c];
            float x  = xs[d];
            float s  = x - ev;
            float bb = s - x;
            float err = (x - (s - bb)) + ((-ev) - bb);
            float pq = s * s;
            float pe = fmaf(s, s, -pq);
            float cross = fmaf(2.f * s, err, fmaf(err, err, pe));
            float t1  = hi + pq;
            float bb2 = t1 - hi;
            float e2  = (hi - (t1 - bb2)) + (pq - bb2);
            hi = t1;
            lo += e2 + cross;
        }
        float th = hi + lo;
        float tl = lo - (th - hi);

        rh[tid] = th; rl[tid] = tl; rix[tid] = c;
        __syncthreads();
#pragma unroll
        for (int s = 512; s; s >>= 1) {
            if (tid < s) {
                float oh = rh[tid + s], ol = rl[tid + s];
                int   oi = rix[tid + s];
                float mh = rh[tid], ml = rl[tid];
                int   mi = rix[tid];
                if (oh < mh || (oh == mh && (ol < ml || (ol == ml && oi < mi)))) {
                    rh[tid] = oh; rl[tid] = ol; rix[tid] = oi;
                }
            }
            __syncthreads();
        }
        if (tid == 0) g_idx[lvl][p] = rix[0];
    }
}

// ---------------- kernel: gather z_q + per-block loss partials ----------------
__global__ __launch_bounds__(256)
void gather_kernel(const float* __restrict__ h_top, const float* __restrict__ h_bot,
                   const float* __restrict__ cb_top, const float* __restrict__ cb_bot,
                   float* __restrict__ out) {
    int lvl = blockIdx.z;
    const float* h  = lvl ? h_bot  : h_top;
    const float* cb = lvl ? cb_bot : cb_top;
    float* z = out + (size_t)lvl * NELEM;

    int b = blockIdx.y;
    int t0 = blockIdx.x * 32;
    int tid = threadIdx.x;

    __shared__ int   sidx[32];
    __shared__ float sh[32 * 33];
    __shared__ float red[256];

    if (tid < 32) sidx[tid] = g_idx[lvl][b * TLEN + t0 + tid];
    __syncthreads();

    float lacc = 0.f;
    int j2 = tid >> 3, l8 = tid & 7;

    for (int dc = 0; dc < DIM; dc += 32) {
        float4 v = *(const float4*)(cb + (size_t)sidx[j2] * DIM + dc + l8 * 4);
        sh[(l8 * 4 + 0) * 33 + j2] = v.x;
        sh[(l8 * 4 + 1) * 33 + j2] = v.y;
        sh[(l8 * 4 + 2) * 33 + j2] = v.z;
        sh[(l8 * 4 + 3) * 33 + j2] = v.w;
        __syncthreads();
#pragma unroll
        for (int it = 0; it < 4; it++) {
            int i = tid + it * 256;
            int dl = i >> 5, j = i & 31;
            size_t off = ((size_t)b * DIM + dc + dl) * TLEN + t0 + j;
            float zz = sh[dl * 33 + j];
            z[off] = zz;
            float e = h[off] - zz;
            lacc = fmaf(e, e, lacc);
        }
        __syncthreads();
    }

    red[tid] = lacc;
    __syncthreads();
#pragma unroll
    for (int s = 128; s; s >>= 1) {
        if (tid < s) red[tid] += red[tid + s];
        __syncthreads();
    }
    if (tid == 0) g_partial[lvl][blockIdx.y * (TLEN / 32) + blockIdx.x] = red[0];
}

// ---------------- kernel: finalize scalars ----------------
__global__ __launch_bounds__(1024)
void finalize_kernel(float* __restrict__ out) {
    __shared__ int   hist[KCODES];
    __shared__ float red[1024];
    int tid = threadIdx.x;

    float sums[2];
#pragma unroll
    for (int lvl = 0; lvl < 2; lvl++) {
        red[tid] = g_partial[lvl][tid];
        __syncthreads();
        for (int s = 512; s; s >>= 1) {
            if (tid < s) red[tid] += red[tid + s];
            __syncthreads();
        }
        sums[lvl] = red[0];
        __syncthreads();
    }
    float loss = sums[0] * (1.f / (float)NELEM) + sums[1] * (1.f / (float)NELEM);

    float ppl[2];
#pragma unroll
    for (int lvl = 0; lvl < 2; lvl++) {
        hist[tid] = 0;
        __syncthreads();
#pragma unroll
        for (int i = 0; i < NPTS / 1024; i++)
            atomicAdd(&hist[g_idx[lvl][i * 1024 + tid]], 1);
        __syncthreads();
        float p = (float)hist[tid] * (1.f / (float)NPTS);
        red[tid] = p * logf(p + 1e-10f);
        __syncthreads();
        for (int s = 512; s; s >>= 1) {
            if (tid < s) red[tid] += red[tid + s];
            __syncthreads();
        }
        ppl[lvl] = expf(-red[0]);
        __syncthreads();
    }

    if (tid == 0) {
        size_t base = (size_t)2 * NELEM;
        out[base + 0] = loss;
        out[base + 1] = loss;
        out[base + 2] = ppl[0];
        out[base + 3] = ppl[1];
    }
}

// ---------------- launcher ----------------
extern "C" void kernel_launch(void* const* d_in, const int* in_sizes, int n_in,
                              void* d_out, int out_size) {
    const float* h_top  = (const float*)d_in[0];
    const float* h_bot  = (const float*)d_in[1];
    const float* cb_top = (const float*)d_in[2];
    const float* cb_bot = (const float*)d_in[3];
    float* out = (float*)d_out;

    cudaFuncSetAttribute(argmin_kernel,
                         cudaFuncAttributeMaxDynamicSharedMemorySize, ARG_SMEM);

    xsplit_kernel<<<dim3(TLEN / 32, DIM / 64, BATCH * LEVELS), 256>>>(h_top, h_bot);
    ecnorm_kernel<<<dim3(KCODES / 8, LEVELS), 256>>>(cb_top, cb_bot);
    btrans_kernel<<<dim3(KCODES / 32, DIM / 32, LEVELS), 256>>>(cb_top, cb_bot);
    argmin_kernel<<<296, 256, ARG_SMEM>>>();
    refine_kernel<<<dim3(512, LEVELS), 1024>>>(h_top, h_bot);
    gather_kernel<<<dim3(TLEN / 32, BATCH, LEVELS), 256>>>(h_top, h_bot, cb_top, cb_bot, out);
    finalize_kernel<<<1, 1024>>>(out);
}